// round 1
// baseline (speedup 1.0000x reference)
#include <cuda_runtime.h>
#include <math.h>

// ---------------- problem constants ----------------
#define NB 2
#define NT 2048
#define NC 2048
#define NH 16
#define ND 128
#define C3 (3 * NC)      /* 6144 */
#define BT (NB * NT)     /* 4096 */

#define RMS_EPS 1.1920929e-07f
#define SM_SCALE (1.0f / 128.0f)

// ---------------- scratch (device globals; no allocs allowed) ----------------
__device__ float g_qkv[(size_t)BT * C3];   // ~100.7 MB
__device__ float g_y[(size_t)BT * NC];     // ~33.6 MB
__device__ float g_cos[NT * 64];
__device__ float g_sin[NT * 64];

// ============================================================
// RoPE tables (double precision; tiny kernel)
// ============================================================
__global__ void rope_tables_kernel() {
    int idx = blockIdx.x * blockDim.x + threadIdx.x;
    if (idx >= NT * 64) return;
    int t = idx >> 6;
    int i = idx & 63;
    double inv_f = exp(-((double)i / 64.0) * log(1.0e6));
    double ang = (double)t * inv_f;
    g_cos[idx] = (float)cos(ang);
    g_sin[idx] = (float)sin(ang);
}

// ============================================================
// Tiled fp32 GEMM: C[M,N] = A[M,K] @ B[K,N], all row-major.
// 128x128 block tile, BK=16, 256 threads, 8x8 per thread
// (split 4+4 register tiling for conflict-free LDS.128).
// Requires M%128==0, N%128==0, K%16==0.
// ============================================================
__global__ __launch_bounds__(256) void gemm128_kernel(
    const float* __restrict__ A, const float* __restrict__ Bm,
    float* __restrict__ Cm, int M, int N, int K)
{
    __shared__ float As[2][16][132];
    __shared__ float Bs[2][16][132];

    const int tid = threadIdx.x;
    const int tx = tid & 15;
    const int ty = tid >> 4;
    const int m0 = blockIdx.y << 7;
    const int n0 = blockIdx.x << 7;

    // A-tile load coords: two float4 per thread
    const int ar  = tid >> 2;          // 0..63 (second load: +64)
    const int akc = (tid & 3) << 2;    // k within tile: 0,4,8,12
    // B-tile load coords
    const int br  = tid >> 5;          // 0..7 (second: +8)
    const int bc  = (tid & 31) << 2;   // col within tile

    float acc[8][8];
#pragma unroll
    for (int i = 0; i < 8; i++)
#pragma unroll
        for (int j = 0; j < 8; j++) acc[i][j] = 0.0f;

    float4 pa0, pa1, pb0, pb1;

    // prologue: tile 0
    pa0 = *(const float4*)(A + (size_t)(m0 + ar) * K + akc);
    pa1 = *(const float4*)(A + (size_t)(m0 + ar + 64) * K + akc);
    pb0 = *(const float4*)(Bm + (size_t)br * N + n0 + bc);
    pb1 = *(const float4*)(Bm + (size_t)(br + 8) * N + n0 + bc);

    As[0][akc + 0][ar] = pa0.x; As[0][akc + 1][ar] = pa0.y;
    As[0][akc + 2][ar] = pa0.z; As[0][akc + 3][ar] = pa0.w;
    As[0][akc + 0][ar + 64] = pa1.x; As[0][akc + 1][ar + 64] = pa1.y;
    As[0][akc + 2][ar + 64] = pa1.z; As[0][akc + 3][ar + 64] = pa1.w;
    *(float4*)&Bs[0][br][bc] = pb0;
    *(float4*)&Bs[0][br + 8][bc] = pb1;
    __syncthreads();

    const int nt = K >> 4;
    int buf = 0;
    for (int t = 0; t < nt; ++t) {
        if (t + 1 < nt) {
            int k0 = (t + 1) << 4;
            pa0 = *(const float4*)(A + (size_t)(m0 + ar) * K + k0 + akc);
            pa1 = *(const float4*)(A + (size_t)(m0 + ar + 64) * K + k0 + akc);
            pb0 = *(const float4*)(Bm + (size_t)(k0 + br) * N + n0 + bc);
            pb1 = *(const float4*)(Bm + (size_t)(k0 + br + 8) * N + n0 + bc);
        }
#pragma unroll
        for (int k = 0; k < 16; k++) {
            float a[8], b[8];
            *(float4*)&a[0] = *(float4*)&As[buf][k][ty << 2];
            *(float4*)&a[4] = *(float4*)&As[buf][k][64 + (ty << 2)];
            *(float4*)&b[0] = *(float4*)&Bs[buf][k][tx << 2];
            *(float4*)&b[4] = *(float4*)&Bs[buf][k][64 + (tx << 2)];
#pragma unroll
            for (int i = 0; i < 8; i++)
#pragma unroll
                for (int j = 0; j < 8; j++)
                    acc[i][j] += a[i] * b[j];
        }
        if (t + 1 < nt) {
            int nb = buf ^ 1;
            As[nb][akc + 0][ar] = pa0.x; As[nb][akc + 1][ar] = pa0.y;
            As[nb][akc + 2][ar] = pa0.z; As[nb][akc + 3][ar] = pa0.w;
            As[nb][akc + 0][ar + 64] = pa1.x; As[nb][akc + 1][ar + 64] = pa1.y;
            As[nb][akc + 2][ar + 64] = pa1.z; As[nb][akc + 3][ar + 64] = pa1.w;
            *(float4*)&Bs[nb][br][bc] = pb0;
            *(float4*)&Bs[nb][br + 8][bc] = pb1;
            __syncthreads();
            buf = nb;
        }
    }

#pragma unroll
    for (int i = 0; i < 8; i++) {
        int row = m0 + ((i < 4) ? ((ty << 2) + i) : (64 + (ty << 2) + i - 4));
        float4 c0 = make_float4(acc[i][0], acc[i][1], acc[i][2], acc[i][3]);
        float4 c1 = make_float4(acc[i][4], acc[i][5], acc[i][6], acc[i][7]);
        *(float4*)(Cm + (size_t)row * N + n0 + (tx << 2)) = c0;
        *(float4*)(Cm + (size_t)row * N + n0 + 64 + (tx << 2)) = c1;
    }
}

// ============================================================
// RMSNorm + RoPE in-place on q,k sections of g_qkv.
// 1 block per token (B*T blocks), 8 warps; each warp processes
// 4 head-rows (16 q heads + 16 k heads = 32 tasks).
// ============================================================
__global__ __launch_bounds__(256) void rmsrope_kernel(
    const float* __restrict__ qw, const float* __restrict__ kw)
{
    const int tok = blockIdx.x;          // 0..BT-1
    const int t = tok & (NT - 1);        // position within sequence
    const int warp = threadIdx.x >> 5;
    const int lane = threadIdx.x & 31;

    const float c0 = g_cos[t * 64 + lane];
    const float s0 = g_sin[t * 64 + lane];
    const float c1 = g_cos[t * 64 + 32 + lane];
    const float s1 = g_sin[t * 64 + 32 + lane];

#pragma unroll
    for (int s = 0; s < 4; s++) {
        int task = warp + (s << 3);         // 0..31
        int isK = task >> 4;
        int h = task & 15;
        const float* w = isK ? kw : qw;
        size_t rbase = (size_t)tok * C3 + (size_t)isK * 2048 + (size_t)h * ND;

        float x0 = g_qkv[rbase + lane];
        float x1 = g_qkv[rbase + lane + 32];
        float x2 = g_qkv[rbase + lane + 64];
        float x3 = g_qkv[rbase + lane + 96];

        float ss = x0 * x0 + x1 * x1 + x2 * x2 + x3 * x3;
#pragma unroll
        for (int off = 16; off > 0; off >>= 1)
            ss += __shfl_xor_sync(0xffffffffu, ss, off);
        float inv = 1.0f / sqrtf(ss * (1.0f / (float)ND) + RMS_EPS);

        float n0 = x0 * inv * w[lane];
        float n1 = x1 * inv * w[lane + 32];
        float n2 = x2 * inv * w[lane + 64];
        float n3 = x3 * inv * w[lane + 96];

        // rotate_half pairing: (d, d+64)
        g_qkv[rbase + lane]       = n0 * c0 - n2 * s0;
        g_qkv[rbase + lane + 32]  = n1 * c1 - n3 * s1;
        g_qkv[rbase + lane + 64]  = n2 * c0 + n0 * s0;
        g_qkv[rbase + lane + 96]  = n3 * c1 + n1 * s1;
    }
}

// ============================================================
// Flash attention (fp32, causal, scale = 1/D).
// grid = (T/64, B*H), 256 threads. 64 q-rows x 64 k-cols tiles.
// Thread (ty,tx): S rows {ty,ty+16,ty+32,ty+48}, S cols {4tx..4tx+3},
// O cols {4tx..4tx+3, 64+4tx..64+4tx+3}.
// smem: Qts[128][68] Kts[128][68] Vs[64][132] Ps[64][68] = 120832 B
// ============================================================
#define FLASH_SMEM_FLOATS (128 * 68 + 128 * 68 + 64 * 132 + 64 * 68)
#define FLASH_SMEM_BYTES (FLASH_SMEM_FLOATS * 4)

__global__ __launch_bounds__(256) void flash_kernel()
{
    extern __shared__ float sm[];
    float* Qts = sm;                    // [128][68], d-major
    float* Kts = Qts + 128 * 68;        // [128][68], d-major
    float* Vs  = Kts + 128 * 68;        // [64][132], row-major
    float* Ps  = Vs + 64 * 132;         // [64][68]

    const int tid = threadIdx.x;
    const int tx = tid & 15;
    const int ty = tid >> 4;
    const int qb = blockIdx.x;
    const int bh = blockIdx.y;
    const int b = bh / NH;
    const int h = bh % NH;
    const int q0 = qb << 6;

    const size_t base = (size_t)b * NT * C3 + (size_t)h * ND;

    // Load Q tile transposed: Qts[d][r]
#pragma unroll
    for (int i = 0; i < 8; i++) {
        int f = tid + (i << 8);
        int r = f >> 5;
        int d4 = (f & 31) << 2;
        float4 v = *(const float4*)&g_qkv[base + (size_t)(q0 + r) * C3 + d4];
        Qts[(d4 + 0) * 68 + r] = v.x;
        Qts[(d4 + 1) * 68 + r] = v.y;
        Qts[(d4 + 2) * 68 + r] = v.z;
        Qts[(d4 + 3) * 68 + r] = v.w;
    }

    float o[4][8];
#pragma unroll
    for (int i = 0; i < 4; i++)
#pragma unroll
        for (int j = 0; j < 8; j++) o[i][j] = 0.0f;
    float m_[4], l_[4];
#pragma unroll
    for (int i = 0; i < 4; i++) { m_[i] = -INFINITY; l_[i] = 0.0f; }

    const int nkb = qb + 1;
    for (int kb = 0; kb < nkb; kb++) {
        __syncthreads();   // protects Kts/Vs/Ps from previous iteration readers
        const int k0 = kb << 6;

        // Load K (transposed) and V tiles
#pragma unroll
        for (int i = 0; i < 8; i++) {
            int f = tid + (i << 8);
            int r = f >> 5;
            int d4 = (f & 31) << 2;
            size_t grow = base + (size_t)(k0 + r) * C3;
            float4 kv = *(const float4*)&g_qkv[grow + 2048 + d4];
            Kts[(d4 + 0) * 68 + r] = kv.x;
            Kts[(d4 + 1) * 68 + r] = kv.y;
            Kts[(d4 + 2) * 68 + r] = kv.z;
            Kts[(d4 + 3) * 68 + r] = kv.w;
            float4 vv = *(const float4*)&g_qkv[grow + 4096 + d4];
            *(float4*)&Vs[r * 132 + d4] = vv;
        }
        __syncthreads();

        // S = Q @ K^T
        float s[4][4];
#pragma unroll
        for (int i = 0; i < 4; i++)
#pragma unroll
            for (int j = 0; j < 4; j++) s[i][j] = 0.0f;

#pragma unroll 4
        for (int d = 0; d < ND; d++) {
            float q0v = Qts[d * 68 + ty];
            float q1v = Qts[d * 68 + ty + 16];
            float q2v = Qts[d * 68 + ty + 32];
            float q3v = Qts[d * 68 + ty + 48];
            float4 kk = *(float4*)&Kts[d * 68 + (tx << 2)];
            s[0][0] += q0v * kk.x; s[0][1] += q0v * kk.y; s[0][2] += q0v * kk.z; s[0][3] += q0v * kk.w;
            s[1][0] += q1v * kk.x; s[1][1] += q1v * kk.y; s[1][2] += q1v * kk.z; s[1][3] += q1v * kk.w;
            s[2][0] += q2v * kk.x; s[2][1] += q2v * kk.y; s[2][2] += q2v * kk.z; s[2][3] += q2v * kk.w;
            s[3][0] += q3v * kk.x; s[3][1] += q3v * kk.y; s[3][2] += q3v * kk.z; s[3][3] += q3v * kk.w;
        }

        // scale + causal mask + online softmax (row groups share 16 lanes)
#pragma unroll
        for (int i = 0; i < 4; i++) {
            int qi = q0 + ty + (i << 4);
#pragma unroll
            for (int j = 0; j < 4; j++) {
                int kj = k0 + (tx << 2) + j;
                float v = s[i][j] * SM_SCALE;
                s[i][j] = (kj <= qi) ? v : -1e30f;
            }
            float rm = fmaxf(fmaxf(s[i][0], s[i][1]), fmaxf(s[i][2], s[i][3]));
            rm = fmaxf(rm, __shfl_xor_sync(0xffffffffu, rm, 1));
            rm = fmaxf(rm, __shfl_xor_sync(0xffffffffu, rm, 2));
            rm = fmaxf(rm, __shfl_xor_sync(0xffffffffu, rm, 4));
            rm = fmaxf(rm, __shfl_xor_sync(0xffffffffu, rm, 8));
            float mn = fmaxf(m_[i], rm);
            float corr = expf(m_[i] - mn);
            float rs = 0.0f;
#pragma unroll
            for (int j = 0; j < 4; j++) {
                float p = expf(s[i][j] - mn);
                s[i][j] = p;
                rs += p;
            }
            rs += __shfl_xor_sync(0xffffffffu, rs, 1);
            rs += __shfl_xor_sync(0xffffffffu, rs, 2);
            rs += __shfl_xor_sync(0xffffffffu, rs, 4);
            rs += __shfl_xor_sync(0xffffffffu, rs, 8);
            l_[i] = l_[i] * corr + rs;
            m_[i] = mn;
#pragma unroll
            for (int c = 0; c < 8; c++) o[i][c] *= corr;
            *(float4*)&Ps[(ty + (i << 4)) * 68 + (tx << 2)] =
                make_float4(s[i][0], s[i][1], s[i][2], s[i][3]);
        }
        __syncthreads();

        // O += P @ V
#pragma unroll 2
        for (int j = 0; j < 64; j++) {
            float p0 = Ps[ty * 68 + j];
            float p1 = Ps[(ty + 16) * 68 + j];
            float p2 = Ps[(ty + 32) * 68 + j];
            float p3 = Ps[(ty + 48) * 68 + j];
            float4 va = *(float4*)&Vs[j * 132 + (tx << 2)];
            float4 vb = *(float4*)&Vs[j * 132 + 64 + (tx << 2)];
            o[0][0] += p0 * va.x; o[0][1] += p0 * va.y; o[0][2] += p0 * va.z; o[0][3] += p0 * va.w;
            o[0][4] += p0 * vb.x; o[0][5] += p0 * vb.y; o[0][6] += p0 * vb.z; o[0][7] += p0 * vb.w;
            o[1][0] += p1 * va.x; o[1][1] += p1 * va.y; o[1][2] += p1 * va.z; o[1][3] += p1 * va.w;
            o[1][4] += p1 * vb.x; o[1][5] += p1 * vb.y; o[1][6] += p1 * vb.z; o[1][7] += p1 * vb.w;
            o[2][0] += p2 * va.x; o[2][1] += p2 * va.y; o[2][2] += p2 * va.z; o[2][3] += p2 * va.w;
            o[2][4] += p2 * vb.x; o[2][5] += p2 * vb.y; o[2][6] += p2 * vb.z; o[2][7] += p2 * vb.w;
            o[3][0] += p3 * va.x; o[3][1] += p3 * va.y; o[3][2] += p3 * va.z; o[3][3] += p3 * va.w;
            o[3][4] += p3 * vb.x; o[3][5] += p3 * vb.y; o[3][6] += p3 * vb.z; o[3][7] += p3 * vb.w;
        }
    }

    // epilogue: O /= l, write to g_y[b, row, h*128 + d]
#pragma unroll
    for (int i = 0; i < 4; i++) {
        float inv = 1.0f / l_[i];
        int row = q0 + ty + (i << 4);
        size_t ybase = ((size_t)b * NT + row) * NC + (size_t)h * ND;
        float4 r0 = make_float4(o[i][0] * inv, o[i][1] * inv, o[i][2] * inv, o[i][3] * inv);
        float4 r1 = make_float4(o[i][4] * inv, o[i][5] * inv, o[i][6] * inv, o[i][7] * inv);
        *(float4*)&g_y[ybase + (tx << 2)] = r0;
        *(float4*)&g_y[ybase + 64 + (tx << 2)] = r1;
    }
}

// ============================================================
// launch
// ============================================================
extern "C" void kernel_launch(void* const* d_in, const int* in_sizes, int n_in,
                              void* d_out, int out_size)
{
    const float* x      = (const float*)d_in[0];
    const float* w_qkv  = (const float*)d_in[1];
    const float* w_proj = (const float*)d_in[2];
    const float* qw     = (const float*)d_in[3];
    const float* kw     = (const float*)d_in[4];
    float* out = (float*)d_out;

    float* qkv_ptr = nullptr;
    float* y_ptr = nullptr;
    cudaGetSymbolAddress((void**)&qkv_ptr, g_qkv);
    cudaGetSymbolAddress((void**)&y_ptr, g_y);

    // 1. RoPE tables
    rope_tables_kernel<<<(NT * 64 + 255) / 256, 256>>>();

    // 2. qkv = x @ w_qkv   [4096,2048]x[2048,6144]
    {
        dim3 grid(C3 / 128, BT / 128);
        gemm128_kernel<<<grid, 256>>>(x, w_qkv, qkv_ptr, BT, C3, NC);
    }

    // 3. RMSNorm + RoPE on q,k
    rmsrope_kernel<<<BT, 256>>>(qw, kw);

    // 4. flash attention
    {
        cudaFuncSetAttribute(flash_kernel,
                             cudaFuncAttributeMaxDynamicSharedMemorySize,
                             FLASH_SMEM_BYTES);
        dim3 grid(NT / 64, NB * NH);
        flash_kernel<<<grid, 256, FLASH_SMEM_BYTES>>>();
    }

    // 5. out = y @ w_proj  [4096,2048]x[2048,2048]
    {
        dim3 grid(NC / 128, BT / 128);
        gemm128_kernel<<<grid, 256>>>(y_ptr, w_proj, out, BT, NC, NC);
    }
}

// round 3
// speedup vs baseline: 1.7634x; 1.7634x over previous
#include <cuda_runtime.h>
#include <math.h>
#include <stdint.h>

// ---------------- problem constants ----------------
#define NB 2
#define NT 2048
#define NC 2048
#define NH 16
#define ND 128
#define C3 (3 * NC)      /* 6144 */
#define BT (NB * NT)     /* 4096 */

#define RMS_EPS 1.1920929e-07f
#define SM_SCALE (1.0f / 128.0f)

// ---------------- scratch (device globals; no allocs allowed) ----------------
__device__ float g_qkv[(size_t)BT * C3];      // ~100.7 MB
__device__ float g_y[(size_t)BT * NC];        // ~33.6 MB  (tf32-rounded by flash epilogue)
__device__ float g_xt[(size_t)BT * NC];       // ~33.6 MB  (x, tf32-rounded)
__device__ float g_wqkvT[(size_t)C3 * NC];    // ~50.3 MB  (w_qkv^T, tf32-rounded)
__device__ float g_wprojT[(size_t)NC * NC];   // ~16.8 MB  (w_proj^T, tf32-rounded)
__device__ float g_cos[NT * 64];
__device__ float g_sin[NT * 64];

// ---------------- helpers ----------------
__device__ __forceinline__ float tf32r(float x) {
    uint32_t o;
    asm("cvt.rna.tf32.f32 %0, %1;" : "=r"(o) : "f"(x));
    return __uint_as_float(o);
}

__device__ __forceinline__ void mma_tf32(float c[4],
                                         uint32_t a0, uint32_t a1, uint32_t a2, uint32_t a3,
                                         uint32_t b0, uint32_t b1) {
    asm volatile(
        "mma.sync.aligned.m16n8k8.row.col.f32.tf32.tf32.f32 "
        "{%0,%1,%2,%3}, {%4,%5,%6,%7}, {%8,%9}, {%0,%1,%2,%3};"
        : "+f"(c[0]), "+f"(c[1]), "+f"(c[2]), "+f"(c[3])
        : "r"(a0), "r"(a1), "r"(a2), "r"(a3), "r"(b0), "r"(b1));
}

// ============================================================
// RoPE tables (double precision; tiny kernel)
// ============================================================
__global__ void rope_tables_kernel() {
    int idx = blockIdx.x * blockDim.x + threadIdx.x;
    if (idx >= NT * 64) return;
    int t = idx >> 6;
    int i = idx & 63;
    double inv_f = exp(-((double)i / 64.0) * log(1.0e6));
    double ang = (double)t * inv_f;
    g_cos[idx] = (float)cos(ang);
    g_sin[idx] = (float)sin(ang);
}

// ============================================================
// tf32-round copy: out[i] = round_tf32(in[i]), float4 vectorized
// ============================================================
__global__ __launch_bounds__(256) void cvt_copy_kernel(
    const float4* __restrict__ in, float4* __restrict__ out, int n4)
{
    int i = blockIdx.x * blockDim.x + threadIdx.x;
    if (i >= n4) return;
    float4 v = in[i];
    v.x = tf32r(v.x); v.y = tf32r(v.y); v.z = tf32r(v.z); v.w = tf32r(v.w);
    out[i] = v;
}

// ============================================================
// Transpose + tf32 round: out[C][R] = tf32(in[R][C])
// ============================================================
__global__ __launch_bounds__(256) void transpose_kernel(
    const float* __restrict__ in, float* __restrict__ out, int R, int Ccols)
{
    __shared__ float tile[32][33];
    int c0 = blockIdx.x * 32, r0 = blockIdx.y * 32;
    int tx = threadIdx.x, ty = threadIdx.y;
#pragma unroll
    for (int j = 0; j < 32; j += 8)
        tile[ty + j][tx] = in[(size_t)(r0 + ty + j) * Ccols + c0 + tx];
    __syncthreads();
#pragma unroll
    for (int j = 0; j < 32; j += 8)
        out[(size_t)(c0 + ty + j) * R + r0 + tx] = tf32r(tile[tx][ty + j]);
}

// ============================================================
// tf32 mma.sync GEMM: C[M,N] = A[M,K] @ Bt[N,K]^T
// Inputs must already be tf32-rounded. 128x128 tile, BK=32,
// 256 thr = 8 warps (2m x 4n), warp tile 64x32, double-buffered.
// smem: per stage A[128][36] + B[128][36]; 2 stages = 73728 B.
// ============================================================
#define GMM_STAGE 9216                     /* floats per stage (A+B) */
#define GMM_SMEM_BYTES (2 * GMM_STAGE * 4) /* 73728 */

__global__ __launch_bounds__(256) void gemm_mma_kernel(
    const float* __restrict__ A, const float* __restrict__ Bt,
    float* __restrict__ Cm, int M, int N, int K)
{
    extern __shared__ float sm[];

    const int tid = threadIdx.x;
    const int wid = tid >> 5;
    const int lane = tid & 31;
    const int gid = lane >> 2;   // 0..7
    const int tig = lane & 3;    // 0..3
    const int warp_m = wid & 1;  // 0..1 -> 64-row half
    const int warp_n = wid >> 1; // 0..3 -> 32-col quarter
    const int m0 = blockIdx.y << 7;
    const int n0 = blockIdx.x << 7;

    const int ar = tid >> 3;        // 0..31 (rows, +32*i)
    const int ak = (tid & 7) << 2;  // k offset 0..28

    float acc[4][4][4];
#pragma unroll
    for (int i = 0; i < 4; i++)
#pragma unroll
        for (int j = 0; j < 4; j++)
#pragma unroll
            for (int k = 0; k < 4; k++) acc[i][j][k] = 0.0f;

    float4 ra[4], rb[4];
    // LDG tile 0
#pragma unroll
    for (int i = 0; i < 4; i++) {
        ra[i] = *(const float4*)(A + (size_t)(m0 + ar + (i << 5)) * K + ak);
        rb[i] = *(const float4*)(Bt + (size_t)(n0 + ar + (i << 5)) * K + ak);
    }
    // STS stage 0
    {
        float* As = sm;
        float* Bs = sm + 4608;
#pragma unroll
        for (int i = 0; i < 4; i++) {
            int r = ar + (i << 5);
            *(float4*)&As[r * 36 + ak] = ra[i];
            *(float4*)&Bs[r * 36 + ak] = rb[i];
        }
    }
    __syncthreads();

    const int nt = K >> 5;
    for (int t = 0; t < nt; t++) {
        const int buf = t & 1;
        if (t + 1 < nt) {
            const int k0 = (t + 1) << 5;
#pragma unroll
            for (int i = 0; i < 4; i++) {
                ra[i] = *(const float4*)(A + (size_t)(m0 + ar + (i << 5)) * K + k0 + ak);
                rb[i] = *(const float4*)(Bt + (size_t)(n0 + ar + (i << 5)) * K + k0 + ak);
            }
        }

        // compute on buf
        {
            const uint32_t* Au = (const uint32_t*)(sm + buf * GMM_STAGE);
            const uint32_t* Bu = Au + 4608;
            const int mbase = warp_m << 6;
            const int nbase = warp_n << 5;
#pragma unroll
            for (int ks = 0; ks < 4; ks++) {
                const int kb = ks << 3;
                uint32_t af[4][4];
#pragma unroll
                for (int mf = 0; mf < 4; mf++) {
                    int r0_ = (mbase + (mf << 4) + gid) * 36 + kb + tig;
                    af[mf][0] = Au[r0_];
                    af[mf][1] = Au[r0_ + 8 * 36];
                    af[mf][2] = Au[r0_ + 4];
                    af[mf][3] = Au[r0_ + 8 * 36 + 4];
                }
                uint32_t bf[4][2];
#pragma unroll
                for (int nf = 0; nf < 4; nf++) {
                    int nr = (nbase + (nf << 3) + gid) * 36 + kb + tig;
                    bf[nf][0] = Bu[nr];
                    bf[nf][1] = Bu[nr + 4];
                }
#pragma unroll
                for (int mf = 0; mf < 4; mf++)
#pragma unroll
                    for (int nf = 0; nf < 4; nf++)
                        mma_tf32(acc[mf][nf], af[mf][0], af[mf][1], af[mf][2], af[mf][3],
                                 bf[nf][0], bf[nf][1]);
            }
        }

        if (t + 1 < nt) {
            float* As = sm + (buf ^ 1) * GMM_STAGE;
            float* Bs = As + 4608;
#pragma unroll
            for (int i = 0; i < 4; i++) {
                int r = ar + (i << 5);
                *(float4*)&As[r * 36 + ak] = ra[i];
                *(float4*)&Bs[r * 36 + ak] = rb[i];
            }
            __syncthreads();
        }
    }

    // epilogue: direct float2 stores
#pragma unroll
    for (int mf = 0; mf < 4; mf++) {
#pragma unroll
        for (int nf = 0; nf < 4; nf++) {
            int r0_ = m0 + (warp_m << 6) + (mf << 4) + gid;
            int c = n0 + (warp_n << 5) + (nf << 3) + (tig << 1);
            *(float2*)&Cm[(size_t)r0_ * N + c] = make_float2(acc[mf][nf][0], acc[mf][nf][1]);
            *(float2*)&Cm[(size_t)(r0_ + 8) * N + c] = make_float2(acc[mf][nf][2], acc[mf][nf][3]);
        }
    }
}

// ============================================================
// RMSNorm + RoPE in-place on q,k sections of g_qkv.
// ============================================================
__global__ __launch_bounds__(256) void rmsrope_kernel(
    const float* __restrict__ qw, const float* __restrict__ kw)
{
    const int tok = blockIdx.x;
    const int t = tok & (NT - 1);
    const int warp = threadIdx.x >> 5;
    const int lane = threadIdx.x & 31;

    const float c0 = g_cos[t * 64 + lane];
    const float s0 = g_sin[t * 64 + lane];
    const float c1 = g_cos[t * 64 + 32 + lane];
    const float s1 = g_sin[t * 64 + 32 + lane];

#pragma unroll
    for (int s = 0; s < 4; s++) {
        int task = warp + (s << 3);
        int isK = task >> 4;
        int h = task & 15;
        const float* w = isK ? kw : qw;
        size_t rbase = (size_t)tok * C3 + (size_t)isK * 2048 + (size_t)h * ND;

        float x0 = g_qkv[rbase + lane];
        float x1 = g_qkv[rbase + lane + 32];
        float x2 = g_qkv[rbase + lane + 64];
        float x3 = g_qkv[rbase + lane + 96];

        float ss = x0 * x0 + x1 * x1 + x2 * x2 + x3 * x3;
#pragma unroll
        for (int off = 16; off > 0; off >>= 1)
            ss += __shfl_xor_sync(0xffffffffu, ss, off);
        float inv = 1.0f / sqrtf(ss * (1.0f / (float)ND) + RMS_EPS);

        float n0 = x0 * inv * w[lane];
        float n1 = x1 * inv * w[lane + 32];
        float n2 = x2 * inv * w[lane + 64];
        float n3 = x3 * inv * w[lane + 96];

        g_qkv[rbase + lane]       = n0 * c0 - n2 * s0;
        g_qkv[rbase + lane + 32]  = n1 * c1 - n3 * s1;
        g_qkv[rbase + lane + 64]  = n2 * c0 + n0 * s0;
        g_qkv[rbase + lane + 96]  = n3 * c1 + n1 * s1;
    }
}

// ============================================================
// Flash attention (fp32, causal, scale = 1/D). SIMT.
// Epilogue rounds output to tf32 for the following mma GEMM.
// ============================================================
#define FLASH_SMEM_FLOATS (128 * 68 + 128 * 68 + 64 * 132 + 64 * 68)
#define FLASH_SMEM_BYTES (FLASH_SMEM_FLOATS * 4)

__global__ __launch_bounds__(256) void flash_kernel()
{
    extern __shared__ float sm[];
    float* Qts = sm;
    float* Kts = Qts + 128 * 68;
    float* Vs  = Kts + 128 * 68;
    float* Ps  = Vs + 64 * 132;

    const int tid = threadIdx.x;
    const int tx = tid & 15;
    const int ty = tid >> 4;
    const int qb = blockIdx.x;
    const int bh = blockIdx.y;
    const int b = bh / NH;
    const int h = bh % NH;
    const int q0 = qb << 6;

    const size_t base = (size_t)b * NT * C3 + (size_t)h * ND;

#pragma unroll
    for (int i = 0; i < 8; i++) {
        int f = tid + (i << 8);
        int r = f >> 5;
        int d4 = (f & 31) << 2;
        float4 v = *(const float4*)&g_qkv[base + (size_t)(q0 + r) * C3 + d4];
        Qts[(d4 + 0) * 68 + r] = v.x;
        Qts[(d4 + 1) * 68 + r] = v.y;
        Qts[(d4 + 2) * 68 + r] = v.z;
        Qts[(d4 + 3) * 68 + r] = v.w;
    }

    float o[4][8];
#pragma unroll
    for (int i = 0; i < 4; i++)
#pragma unroll
        for (int j = 0; j < 8; j++) o[i][j] = 0.0f;
    float m_[4], l_[4];
#pragma unroll
    for (int i = 0; i < 4; i++) { m_[i] = -INFINITY; l_[i] = 0.0f; }

    const int nkb = qb + 1;
    for (int kb = 0; kb < nkb; kb++) {
        __syncthreads();
        const int k0 = kb << 6;

#pragma unroll
        for (int i = 0; i < 8; i++) {
            int f = tid + (i << 8);
            int r = f >> 5;
            int d4 = (f & 31) << 2;
            size_t grow = base + (size_t)(k0 + r) * C3;
            float4 kv = *(const float4*)&g_qkv[grow + 2048 + d4];
            Kts[(d4 + 0) * 68 + r] = kv.x;
            Kts[(d4 + 1) * 68 + r] = kv.y;
            Kts[(d4 + 2) * 68 + r] = kv.z;
            Kts[(d4 + 3) * 68 + r] = kv.w;
            float4 vv = *(const float4*)&g_qkv[grow + 4096 + d4];
            *(float4*)&Vs[r * 132 + d4] = vv;
        }
        __syncthreads();

        float s[4][4];
#pragma unroll
        for (int i = 0; i < 4; i++)
#pragma unroll
            for (int j = 0; j < 4; j++) s[i][j] = 0.0f;

#pragma unroll 4
        for (int d = 0; d < ND; d++) {
            float q0v = Qts[d * 68 + ty];
            float q1v = Qts[d * 68 + ty + 16];
            float q2v = Qts[d * 68 + ty + 32];
            float q3v = Qts[d * 68 + ty + 48];
            float4 kk = *(float4*)&Kts[d * 68 + (tx << 2)];
            s[0][0] += q0v * kk.x; s[0][1] += q0v * kk.y; s[0][2] += q0v * kk.z; s[0][3] += q0v * kk.w;
            s[1][0] += q1v * kk.x; s[1][1] += q1v * kk.y; s[1][2] += q1v * kk.z; s[1][3] += q1v * kk.w;
            s[2][0] += q2v * kk.x; s[2][1] += q2v * kk.y; s[2][2] += q2v * kk.z; s[2][3] += q2v * kk.w;
            s[3][0] += q3v * kk.x; s[3][1] += q3v * kk.y; s[3][2] += q3v * kk.z; s[3][3] += q3v * kk.w;
        }

#pragma unroll
        for (int i = 0; i < 4; i++) {
            int qi = q0 + ty + (i << 4);
#pragma unroll
            for (int j = 0; j < 4; j++) {
                int kj = k0 + (tx << 2) + j;
                float v = s[i][j] * SM_SCALE;
                s[i][j] = (kj <= qi) ? v : -1e30f;
            }
            float rm = fmaxf(fmaxf(s[i][0], s[i][1]), fmaxf(s[i][2], s[i][3]));
            rm = fmaxf(rm, __shfl_xor_sync(0xffffffffu, rm, 1));
            rm = fmaxf(rm, __shfl_xor_sync(0xffffffffu, rm, 2));
            rm = fmaxf(rm, __shfl_xor_sync(0xffffffffu, rm, 4));
            rm = fmaxf(rm, __shfl_xor_sync(0xffffffffu, rm, 8));
            float mn = fmaxf(m_[i], rm);
            float corr = expf(m_[i] - mn);
            float rs = 0.0f;
#pragma unroll
            for (int j = 0; j < 4; j++) {
                float p = expf(s[i][j] - mn);
                s[i][j] = p;
                rs += p;
            }
            rs += __shfl_xor_sync(0xffffffffu, rs, 1);
            rs += __shfl_xor_sync(0xffffffffu, rs, 2);
            rs += __shfl_xor_sync(0xffffffffu, rs, 4);
            rs += __shfl_xor_sync(0xffffffffu, rs, 8);
            l_[i] = l_[i] * corr + rs;
            m_[i] = mn;
#pragma unroll
            for (int c = 0; c < 8; c++) o[i][c] *= corr;
            *(float4*)&Ps[(ty + (i << 4)) * 68 + (tx << 2)] =
                make_float4(s[i][0], s[i][1], s[i][2], s[i][3]);
        }
        __syncthreads();

#pragma unroll 2
        for (int j = 0; j < 64; j++) {
            float p0 = Ps[ty * 68 + j];
            float p1 = Ps[(ty + 16) * 68 + j];
            float p2 = Ps[(ty + 32) * 68 + j];
            float p3 = Ps[(ty + 48) * 68 + j];
            float4 va = *(float4*)&Vs[j * 132 + (tx << 2)];
            float4 vb = *(float4*)&Vs[j * 132 + 64 + (tx << 2)];
            o[0][0] += p0 * va.x; o[0][1] += p0 * va.y; o[0][2] += p0 * va.z; o[0][3] += p0 * va.w;
            o[0][4] += p0 * vb.x; o[0][5] += p0 * vb.y; o[0][6] += p0 * vb.z; o[0][7] += p0 * vb.w;
            o[1][0] += p1 * va.x; o[1][1] += p1 * va.y; o[1][2] += p1 * va.z; o[1][3] += p1 * va.w;
            o[1][4] += p1 * vb.x; o[1][5] += p1 * vb.y; o[1][6] += p1 * vb.z; o[1][7] += p1 * vb.w;
            o[2][0] += p2 * va.x; o[2][1] += p2 * va.y; o[2][2] += p2 * va.z; o[2][3] += p2 * va.w;
            o[2][4] += p2 * vb.x; o[2][5] += p2 * vb.y; o[2][6] += p2 * vb.z; o[2][7] += p2 * vb.w;
            o[3][0] += p3 * va.x; o[3][1] += p3 * va.y; o[3][2] += p3 * va.z; o[3][3] += p3 * va.w;
            o[3][4] += p3 * vb.x; o[3][5] += p3 * vb.y; o[3][6] += p3 * vb.z; o[3][7] += p3 * vb.w;
        }
    }

#pragma unroll
    for (int i = 0; i < 4; i++) {
        float inv = 1.0f / l_[i];
        int row = q0 + ty + (i << 4);
        size_t ybase = ((size_t)b * NT + row) * NC + (size_t)h * ND;
        float4 r0 = make_float4(tf32r(o[i][0] * inv), tf32r(o[i][1] * inv),
                                tf32r(o[i][2] * inv), tf32r(o[i][3] * inv));
        float4 r1 = make_float4(tf32r(o[i][4] * inv), tf32r(o[i][5] * inv),
                                tf32r(o[i][6] * inv), tf32r(o[i][7] * inv));
        *(float4*)&g_y[ybase + (tx << 2)] = r0;
        *(float4*)&g_y[ybase + 64 + (tx << 2)] = r1;
    }
}

// ============================================================
// launch
// ============================================================
extern "C" void kernel_launch(void* const* d_in, const int* in_sizes, int n_in,
                              void* d_out, int out_size)
{
    const float* x      = (const float*)d_in[0];
    const float* w_qkv  = (const float*)d_in[1];
    const float* w_proj = (const float*)d_in[2];
    const float* qw     = (const float*)d_in[3];
    const float* kw     = (const float*)d_in[4];
    float* out = (float*)d_out;

    float* qkv_ptr = nullptr;
    float* y_ptr = nullptr;
    float* xt_ptr = nullptr;
    float* wqkvT_ptr = nullptr;
    float* wprojT_ptr = nullptr;
    cudaGetSymbolAddress((void**)&qkv_ptr, g_qkv);
    cudaGetSymbolAddress((void**)&y_ptr, g_y);
    cudaGetSymbolAddress((void**)&xt_ptr, g_xt);
    cudaGetSymbolAddress((void**)&wqkvT_ptr, g_wqkvT);
    cudaGetSymbolAddress((void**)&wprojT_ptr, g_wprojT);

    cudaFuncSetAttribute(gemm_mma_kernel,
                         cudaFuncAttributeMaxDynamicSharedMemorySize, GMM_SMEM_BYTES);
    cudaFuncSetAttribute(flash_kernel,
                         cudaFuncAttributeMaxDynamicSharedMemorySize, FLASH_SMEM_BYTES);

    // 1. RoPE tables
    rope_tables_kernel<<<(NT * 64 + 255) / 256, 256>>>();

    // 2. tf32-rounded operands: x copy + transposed weights
    {
        int n4 = BT * NC / 4;
        cvt_copy_kernel<<<(n4 + 255) / 256, 256>>>((const float4*)x, (float4*)xt_ptr, n4);
        dim3 blk(32, 8);
        transpose_kernel<<<dim3(C3 / 32, NC / 32), blk>>>(w_qkv, wqkvT_ptr, NC, C3);
        transpose_kernel<<<dim3(NC / 32, NC / 32), blk>>>(w_proj, wprojT_ptr, NC, NC);
    }

    // 3. qkv = x @ w_qkv (tf32 mma.sync)
    {
        dim3 grid(C3 / 128, BT / 128);
        gemm_mma_kernel<<<grid, 256, GMM_SMEM_BYTES>>>(xt_ptr, wqkvT_ptr, qkv_ptr, BT, C3, NC);
    }

    // 4. RMSNorm + RoPE on q,k
    rmsrope_kernel<<<BT, 256>>>(qw, kw);

    // 5. flash attention
    {
        dim3 grid(NT / 64, NB * NH);
        flash_kernel<<<grid, 256, FLASH_SMEM_BYTES>>>();
    }

    // 6. out = y @ w_proj (tf32 mma.sync)
    {
        dim3 grid(NC / 128, BT / 128);
        gemm_mma_kernel<<<grid, 256, GMM_SMEM_BYTES>>>(y_ptr, wprojT_ptr, out, BT, NC, NC);
    }
}

// round 4
// speedup vs baseline: 3.4111x; 1.9345x over previous
#include <cuda_runtime.h>
#include <math.h>
#include <stdint.h>

// ---------------- problem constants ----------------
#define NB 2
#define NT 2048
#define NC 2048
#define NH 16
#define ND 128
#define C3 (3 * NC)      /* 6144 */
#define BT (NB * NT)     /* 4096 */

#define RMS_EPS 1.1920929e-07f
#define SM_SCALE (1.0f / 128.0f)

// ---------------- scratch (device globals; no allocs allowed) ----------------
__device__ float g_qkv[(size_t)BT * C3];      // ~100.7 MB
__device__ float g_y[(size_t)BT * NC];        // ~33.6 MB  (tf32-rounded by flash epilogue)
__device__ float g_xt[(size_t)BT * NC];       // ~33.6 MB  (x, tf32-rounded)
__device__ float g_wqkvT[(size_t)C3 * NC];    // ~50.3 MB  (w_qkv^T, tf32-rounded)
__device__ float g_wprojT[(size_t)NC * NC];   // ~16.8 MB  (w_proj^T, tf32-rounded)
__device__ float g_cos[NT * 64];
__device__ float g_sin[NT * 64];

// ---------------- helpers ----------------
__device__ __forceinline__ float tf32r(float x) {
    uint32_t o;
    asm("cvt.rna.tf32.f32 %0, %1;" : "=r"(o) : "f"(x));
    return __uint_as_float(o);
}

__device__ __forceinline__ void mma_tf32(float c[4],
                                         uint32_t a0, uint32_t a1, uint32_t a2, uint32_t a3,
                                         uint32_t b0, uint32_t b1) {
    asm volatile(
        "mma.sync.aligned.m16n8k8.row.col.f32.tf32.tf32.f32 "
        "{%0,%1,%2,%3}, {%4,%5,%6,%7}, {%8,%9}, {%0,%1,%2,%3};"
        : "+f"(c[0]), "+f"(c[1]), "+f"(c[2]), "+f"(c[3])
        : "r"(a0), "r"(a1), "r"(a2), "r"(a3), "r"(b0), "r"(b1));
}

__device__ __forceinline__ uint32_t smem_u32(const void* p) {
    uint32_t a;
    asm("{ .reg .u64 t; cvta.to.shared.u64 t, %1; cvt.u32.u64 %0, t; }"
        : "=r"(a) : "l"(p));
    return a;
}

__device__ __forceinline__ void cp_async16(uint32_t dst, const void* src) {
    asm volatile("cp.async.cg.shared.global [%0], [%1], 16;" :: "r"(dst), "l"(src));
}
#define CP_COMMIT() asm volatile("cp.async.commit_group;" ::: "memory")
#define CP_WAIT0()  asm volatile("cp.async.wait_group 0;" ::: "memory")

// ============================================================
// RoPE tables (double precision; tiny kernel)
// ============================================================
__global__ void rope_tables_kernel() {
    int idx = blockIdx.x * blockDim.x + threadIdx.x;
    if (idx >= NT * 64) return;
    int t = idx >> 6;
    int i = idx & 63;
    double inv_f = exp(-((double)i / 64.0) * log(1.0e6));
    double ang = (double)t * inv_f;
    g_cos[idx] = (float)cos(ang);
    g_sin[idx] = (float)sin(ang);
}

// ============================================================
// tf32-round copy
// ============================================================
__global__ __launch_bounds__(256) void cvt_copy_kernel(
    const float4* __restrict__ in, float4* __restrict__ out, int n4)
{
    int i = blockIdx.x * blockDim.x + threadIdx.x;
    if (i >= n4) return;
    float4 v = in[i];
    v.x = tf32r(v.x); v.y = tf32r(v.y); v.z = tf32r(v.z); v.w = tf32r(v.w);
    out[i] = v;
}

// ============================================================
// Transpose + tf32 round: out[C][R] = tf32(in[R][C])
// ============================================================
__global__ __launch_bounds__(256) void transpose_kernel(
    const float* __restrict__ in, float* __restrict__ out, int R, int Ccols)
{
    __shared__ float tile[32][33];
    int c0 = blockIdx.x * 32, r0 = blockIdx.y * 32;
    int tx = threadIdx.x, ty = threadIdx.y;
#pragma unroll
    for (int j = 0; j < 32; j += 8)
        tile[ty + j][tx] = in[(size_t)(r0 + ty + j) * Ccols + c0 + tx];
    __syncthreads();
#pragma unroll
    for (int j = 0; j < 32; j += 8)
        out[(size_t)(c0 + ty + j) * R + r0 + tx] = tf32r(tile[tx][ty + j]);
}

// ============================================================
// tf32 mma.sync GEMM: C[M,N] = A[M,K] @ Bt[N,K]^T (unchanged from R3)
// ============================================================
#define GMM_STAGE 9216
#define GMM_SMEM_BYTES (2 * GMM_STAGE * 4)

__global__ __launch_bounds__(256) void gemm_mma_kernel(
    const float* __restrict__ A, const float* __restrict__ Bt,
    float* __restrict__ Cm, int M, int N, int K)
{
    extern __shared__ float sm[];

    const int tid = threadIdx.x;
    const int wid = tid >> 5;
    const int lane = tid & 31;
    const int gid = lane >> 2;
    const int tig = lane & 3;
    const int warp_m = wid & 1;
    const int warp_n = wid >> 1;
    const int m0 = blockIdx.y << 7;
    const int n0 = blockIdx.x << 7;

    const int ar = tid >> 3;
    const int ak = (tid & 7) << 2;

    float acc[4][4][4];
#pragma unroll
    for (int i = 0; i < 4; i++)
#pragma unroll
        for (int j = 0; j < 4; j++)
#pragma unroll
            for (int k = 0; k < 4; k++) acc[i][j][k] = 0.0f;

    float4 ra[4], rb[4];
#pragma unroll
    for (int i = 0; i < 4; i++) {
        ra[i] = *(const float4*)(A + (size_t)(m0 + ar + (i << 5)) * K + ak);
        rb[i] = *(const float4*)(Bt + (size_t)(n0 + ar + (i << 5)) * K + ak);
    }
    {
        float* As = sm;
        float* Bs = sm + 4608;
#pragma unroll
        for (int i = 0; i < 4; i++) {
            int r = ar + (i << 5);
            *(float4*)&As[r * 36 + ak] = ra[i];
            *(float4*)&Bs[r * 36 + ak] = rb[i];
        }
    }
    __syncthreads();

    const int nt = K >> 5;
    for (int t = 0; t < nt; t++) {
        const int buf = t & 1;
        if (t + 1 < nt) {
            const int k0 = (t + 1) << 5;
#pragma unroll
            for (int i = 0; i < 4; i++) {
                ra[i] = *(const float4*)(A + (size_t)(m0 + ar + (i << 5)) * K + k0 + ak);
                rb[i] = *(const float4*)(Bt + (size_t)(n0 + ar + (i << 5)) * K + k0 + ak);
            }
        }
        {
            const uint32_t* Au = (const uint32_t*)(sm + buf * GMM_STAGE);
            const uint32_t* Bu = Au + 4608;
            const int mbase = warp_m << 6;
            const int nbase = warp_n << 5;
#pragma unroll
            for (int ks = 0; ks < 4; ks++) {
                const int kb = ks << 3;
                uint32_t af[4][4];
#pragma unroll
                for (int mf = 0; mf < 4; mf++) {
                    int r0_ = (mbase + (mf << 4) + gid) * 36 + kb + tig;
                    af[mf][0] = Au[r0_];
                    af[mf][1] = Au[r0_ + 8 * 36];
                    af[mf][2] = Au[r0_ + 4];
                    af[mf][3] = Au[r0_ + 8 * 36 + 4];
                }
                uint32_t bf[4][2];
#pragma unroll
                for (int nf = 0; nf < 4; nf++) {
                    int nr = (nbase + (nf << 3) + gid) * 36 + kb + tig;
                    bf[nf][0] = Bu[nr];
                    bf[nf][1] = Bu[nr + 4];
                }
#pragma unroll
                for (int mf = 0; mf < 4; mf++)
#pragma unroll
                    for (int nf = 0; nf < 4; nf++)
                        mma_tf32(acc[mf][nf], af[mf][0], af[mf][1], af[mf][2], af[mf][3],
                                 bf[nf][0], bf[nf][1]);
            }
        }
        if (t + 1 < nt) {
            float* As = sm + (buf ^ 1) * GMM_STAGE;
            float* Bs = As + 4608;
#pragma unroll
            for (int i = 0; i < 4; i++) {
                int r = ar + (i << 5);
                *(float4*)&As[r * 36 + ak] = ra[i];
                *(float4*)&Bs[r * 36 + ak] = rb[i];
            }
            __syncthreads();
        }
    }

#pragma unroll
    for (int mf = 0; mf < 4; mf++) {
#pragma unroll
        for (int nf = 0; nf < 4; nf++) {
            int r0_ = m0 + (warp_m << 6) + (mf << 4) + gid;
            int c = n0 + (warp_n << 5) + (nf << 3) + (tig << 1);
            *(float2*)&Cm[(size_t)r0_ * N + c] = make_float2(acc[mf][nf][0], acc[mf][nf][1]);
            *(float2*)&Cm[(size_t)(r0_ + 8) * N + c] = make_float2(acc[mf][nf][2], acc[mf][nf][3]);
        }
    }
}

// ============================================================
// RMSNorm + RoPE in-place on q,k; tf32-round q,k,v.
// ============================================================
__global__ __launch_bounds__(256) void rmsrope_kernel(
    const float* __restrict__ qw, const float* __restrict__ kw)
{
    const int tok = blockIdx.x;
    const int t = tok & (NT - 1);
    const int warp = threadIdx.x >> 5;
    const int lane = threadIdx.x & 31;

    const float c0 = g_cos[t * 64 + lane];
    const float s0 = g_sin[t * 64 + lane];
    const float c1 = g_cos[t * 64 + 32 + lane];
    const float s1 = g_sin[t * 64 + 32 + lane];

#pragma unroll
    for (int s = 0; s < 4; s++) {
        int task = warp + (s << 3);
        int isK = task >> 4;
        int h = task & 15;
        const float* w = isK ? kw : qw;
        size_t rbase = (size_t)tok * C3 + (size_t)isK * 2048 + (size_t)h * ND;

        float x0 = g_qkv[rbase + lane];
        float x1 = g_qkv[rbase + lane + 32];
        float x2 = g_qkv[rbase + lane + 64];
        float x3 = g_qkv[rbase + lane + 96];

        float ss = x0 * x0 + x1 * x1 + x2 * x2 + x3 * x3;
#pragma unroll
        for (int off = 16; off > 0; off >>= 1)
            ss += __shfl_xor_sync(0xffffffffu, ss, off);
        float inv = 1.0f / sqrtf(ss * (1.0f / (float)ND) + RMS_EPS);

        float n0 = x0 * inv * w[lane];
        float n1 = x1 * inv * w[lane + 32];
        float n2 = x2 * inv * w[lane + 64];
        float n3 = x3 * inv * w[lane + 96];

        g_qkv[rbase + lane]       = tf32r(n0 * c0 - n2 * s0);
        g_qkv[rbase + lane + 32]  = tf32r(n1 * c1 - n3 * s1);
        g_qkv[rbase + lane + 64]  = tf32r(n2 * c0 + n0 * s0);
        g_qkv[rbase + lane + 96]  = tf32r(n3 * c1 + n1 * s1);
    }

    // tf32-round the V section of this token (2048 floats = 512 float4)
    {
        float4* vsec = (float4*)&g_qkv[(size_t)tok * C3 + 4096];
#pragma unroll
        for (int i = 0; i < 2; i++) {
            int idx = threadIdx.x + (i << 8);
            float4 v = vsec[idx];
            v.x = tf32r(v.x); v.y = tf32r(v.y); v.z = tf32r(v.z); v.w = tf32r(v.w);
            vsec[idx] = v;
        }
    }
}

// ============================================================
// Flash attention with tf32 mma.sync (causal, scale = 1/D).
// Block: 64 q-rows; iterates 64-wide k-tiles. 256 thr = 8 warps
// as 4(m)x2(n). K/V double-buffered via cp.async.
// smem floats: Qs[64*132] | {Ks[64*132], Vs[64*136]} x2 | Ps[64*68]
//              | redm[2*64] | reds[2*64]
// ============================================================
#define FK_QS   0
#define FK_STG  17152                       /* Ks(8448)+Vs(8704) */
#define FK_KS(s) (8448 + (s) * FK_STG)
#define FK_VS(s) (8448 + (s) * FK_STG + 8448)
#define FK_PS   42752
#define FK_RM   47104
#define FK_RS   47232
#define FK_FLOATS 47360
#define FK_SMEM_BYTES (FK_FLOATS * 4)       /* 189440 */

__global__ __launch_bounds__(256, 1) void flash_mma_kernel()
{
    extern __shared__ float sm[];
    const uint32_t smb = smem_u32(sm);

    const int tid = threadIdx.x;
    const int lane = tid & 31;
    const int wid = tid >> 5;
    const int gid = lane >> 2;
    const int tig = lane & 3;
    const int wm = wid & 3;          // 4 m-warps (16 rows each)
    const int wn = wid >> 2;         // 2 n-warps
    const int mbase = wm << 4;

    const int qb = blockIdx.x;
    const int bh = blockIdx.y;
    const int b = bh >> 4;
    const int h = bh & 15;
    const int q0 = qb << 6;

    const size_t base = (size_t)b * NT * C3 + (size_t)h * ND;

    // ---- load Q tile (row-major, stride 132) ----
#pragma unroll
    for (int i = 0; i < 8; i++) {
        int f = tid + (i << 8);
        int r = f >> 5;
        int d4 = (f & 31) << 2;
        float4 v = *(const float4*)&g_qkv[base + (size_t)(q0 + r) * C3 + d4];
        *(float4*)&sm[FK_QS + r * 132 + d4] = v;
    }

    // ---- cp.async K/V tile 0 ----
    {
        const int k0 = 0, bufi = 0;
#pragma unroll
        for (int i = 0; i < 8; i++) {
            int f = tid + (i << 8);
            int r = f >> 5;
            int d4 = (f & 31) << 2;
            const float* srcK = &g_qkv[base + (size_t)(k0 + r) * C3 + 2048 + d4];
            const float* srcV = &g_qkv[base + (size_t)(k0 + r) * C3 + 4096 + d4];
            cp_async16(smb + (FK_KS(bufi) + r * 132 + d4) * 4, srcK);
            cp_async16(smb + (FK_VS(bufi) + r * 136 + d4) * 4, srcV);
        }
        CP_COMMIT();
    }

    float o[8][4];
#pragma unroll
    for (int j = 0; j < 8; j++)
#pragma unroll
        for (int e = 0; e < 4; e++) o[j][e] = 0.0f;
    float m0_ = -INFINITY, m1_ = -INFINITY, l0_ = 0.0f, l1_ = 0.0f;

    const uint32_t* Qu = (const uint32_t*)(sm + FK_QS);
    uint32_t* Pu = (uint32_t*)(sm + FK_PS);
    float* Pf = sm + FK_PS;
    float* redm = sm + FK_RM;
    float* reds = sm + FK_RS;

    for (int kt = 0; kt <= qb; kt++) {
        CP_WAIT0();
        __syncthreads();
        if (kt < qb) {
            const int k0n = (kt + 1) << 6;
            const int bufn = (kt + 1) & 1;
#pragma unroll
            for (int i = 0; i < 8; i++) {
                int f = tid + (i << 8);
                int r = f >> 5;
                int d4 = (f & 31) << 2;
                const float* srcK = &g_qkv[base + (size_t)(k0n + r) * C3 + 2048 + d4];
                const float* srcV = &g_qkv[base + (size_t)(k0n + r) * C3 + 4096 + d4];
                cp_async16(smb + (FK_KS(bufn) + r * 132 + d4) * 4, srcK);
                cp_async16(smb + (FK_VS(bufn) + r * 136 + d4) * 4, srcV);
            }
            CP_COMMIT();
        }

        const int bufi = kt & 1;
        const uint32_t* Ku = (const uint32_t*)(sm + FK_KS(bufi));
        const uint32_t* Vu = (const uint32_t*)(sm + FK_VS(bufi));
        const int k0 = kt << 6;

        // ---- S = Q @ K^T (64x64, warp tile 16x32) ----
        float s[4][4];
#pragma unroll
        for (int j = 0; j < 4; j++)
#pragma unroll
            for (int e = 0; e < 4; e++) s[j][e] = 0.0f;

#pragma unroll
        for (int kb = 0; kb < 128; kb += 8) {
            int ai = (mbase + gid) * 132 + kb + tig;
            uint32_t a0 = Qu[ai];
            uint32_t a1 = Qu[ai + 8 * 132];
            uint32_t a2 = Qu[ai + 4];
            uint32_t a3 = Qu[ai + 8 * 132 + 4];
#pragma unroll
            for (int j = 0; j < 4; j++) {
                int nr = ((wn << 5) + (j << 3) + gid) * 132 + kb + tig;
                uint32_t b0 = Ku[nr];
                uint32_t b1 = Ku[nr + 4];
                mma_tf32(s[j], a0, a1, a2, a3, b0, b1);
            }
        }

        // ---- scale + mask ----
        const int r0g = q0 + mbase + gid;
        const int r1g = r0g + 8;
        if (kt == qb) {
#pragma unroll
            for (int j = 0; j < 4; j++) {
                int cbase = k0 + (wn << 5) + (j << 3) + (tig << 1);
                s[j][0] = (cbase     <= r0g) ? s[j][0] * SM_SCALE : -1e30f;
                s[j][1] = (cbase + 1 <= r0g) ? s[j][1] * SM_SCALE : -1e30f;
                s[j][2] = (cbase     <= r1g) ? s[j][2] * SM_SCALE : -1e30f;
                s[j][3] = (cbase + 1 <= r1g) ? s[j][3] * SM_SCALE : -1e30f;
            }
        } else {
#pragma unroll
            for (int j = 0; j < 4; j++) {
                s[j][0] *= SM_SCALE; s[j][1] *= SM_SCALE;
                s[j][2] *= SM_SCALE; s[j][3] *= SM_SCALE;
            }
        }

        // ---- online softmax (cross-warp over 2 n-warps) ----
        float pm0 = fmaxf(fmaxf(s[0][0], s[0][1]), fmaxf(s[1][0], s[1][1]));
        pm0 = fmaxf(pm0, fmaxf(fmaxf(s[2][0], s[2][1]), fmaxf(s[3][0], s[3][1])));
        float pm1 = fmaxf(fmaxf(s[0][2], s[0][3]), fmaxf(s[1][2], s[1][3]));
        pm1 = fmaxf(pm1, fmaxf(fmaxf(s[2][2], s[2][3]), fmaxf(s[3][2], s[3][3])));
        pm0 = fmaxf(pm0, __shfl_xor_sync(0xffffffffu, pm0, 1));
        pm0 = fmaxf(pm0, __shfl_xor_sync(0xffffffffu, pm0, 2));
        pm1 = fmaxf(pm1, __shfl_xor_sync(0xffffffffu, pm1, 1));
        pm1 = fmaxf(pm1, __shfl_xor_sync(0xffffffffu, pm1, 2));
        if (tig == 0) {
            redm[(wn << 6) + mbase + gid] = pm0;
            redm[(wn << 6) + mbase + gid + 8] = pm1;
        }
        __syncthreads();
        float mn0 = fmaxf(m0_, fmaxf(pm0, redm[((wn ^ 1) << 6) + mbase + gid]));
        float mn1 = fmaxf(m1_, fmaxf(pm1, redm[((wn ^ 1) << 6) + mbase + gid + 8]));
        float corr0 = __expf(m0_ - mn0);
        float corr1 = __expf(m1_ - mn1);

        float ps0 = 0.0f, ps1 = 0.0f;
#pragma unroll
        for (int j = 0; j < 4; j++) {
            float p00 = __expf(s[j][0] - mn0);
            float p01 = __expf(s[j][1] - mn0);
            float p10 = __expf(s[j][2] - mn1);
            float p11 = __expf(s[j][3] - mn1);
            ps0 += p00 + p01;
            ps1 += p10 + p11;
            int c = (wn << 5) + (j << 3) + (tig << 1);
            *(float2*)&Pf[(mbase + gid) * 68 + c] = make_float2(tf32r(p00), tf32r(p01));
            *(float2*)&Pf[(mbase + gid + 8) * 68 + c] = make_float2(tf32r(p10), tf32r(p11));
        }
        ps0 += __shfl_xor_sync(0xffffffffu, ps0, 1);
        ps0 += __shfl_xor_sync(0xffffffffu, ps0, 2);
        ps1 += __shfl_xor_sync(0xffffffffu, ps1, 1);
        ps1 += __shfl_xor_sync(0xffffffffu, ps1, 2);
        if (tig == 0) {
            reds[(wn << 6) + mbase + gid] = ps0;
            reds[(wn << 6) + mbase + gid + 8] = ps1;
        }
        __syncthreads();
        l0_ = l0_ * corr0 + ps0 + reds[((wn ^ 1) << 6) + mbase + gid];
        l1_ = l1_ * corr1 + ps1 + reds[((wn ^ 1) << 6) + mbase + gid + 8];
        m0_ = mn0; m1_ = mn1;
#pragma unroll
        for (int j = 0; j < 8; j++) {
            o[j][0] *= corr0; o[j][1] *= corr0;
            o[j][2] *= corr1; o[j][3] *= corr1;
        }

        // ---- O += P @ V (warp tile 16 x 64 d-cols) ----
#pragma unroll
        for (int kb = 0; kb < 64; kb += 8) {
            int ai = (mbase + gid) * 68 + kb + tig;
            uint32_t a0 = Pu[ai];
            uint32_t a1 = Pu[ai + 8 * 68];
            uint32_t a2 = Pu[ai + 4];
            uint32_t a3 = Pu[ai + 8 * 68 + 4];
#pragma unroll
            for (int j = 0; j < 8; j++) {
                int dcol = (wn << 6) + (j << 3) + gid;
                uint32_t b0 = Vu[(kb + tig) * 136 + dcol];
                uint32_t b1 = Vu[(kb + tig + 4) * 136 + dcol];
                mma_tf32(o[j], a0, a1, a2, a3, b0, b1);
            }
        }
    }

    // ---- epilogue ----
    const float inv0 = 1.0f / l0_;
    const float inv1 = 1.0f / l1_;
    const int r0g = q0 + mbase + gid;
    const size_t y0 = ((size_t)b * NT + r0g) * NC + (size_t)h * ND;
    const size_t y1 = y0 + (size_t)8 * NC;
#pragma unroll
    for (int j = 0; j < 8; j++) {
        int c = (wn << 6) + (j << 3) + (tig << 1);
        *(float2*)&g_y[y0 + c] = make_float2(tf32r(o[j][0] * inv0), tf32r(o[j][1] * inv0));
        *(float2*)&g_y[y1 + c] = make_float2(tf32r(o[j][2] * inv1), tf32r(o[j][3] * inv1));
    }
}

// ============================================================
// launch
// ============================================================
extern "C" void kernel_launch(void* const* d_in, const int* in_sizes, int n_in,
                              void* d_out, int out_size)
{
    const float* x      = (const float*)d_in[0];
    const float* w_qkv  = (const float*)d_in[1];
    const float* w_proj = (const float*)d_in[2];
    const float* qw     = (const float*)d_in[3];
    const float* kw     = (const float*)d_in[4];
    float* out = (float*)d_out;

    float* qkv_ptr = nullptr;
    float* y_ptr = nullptr;
    float* xt_ptr = nullptr;
    float* wqkvT_ptr = nullptr;
    float* wprojT_ptr = nullptr;
    cudaGetSymbolAddress((void**)&qkv_ptr, g_qkv);
    cudaGetSymbolAddress((void**)&y_ptr, g_y);
    cudaGetSymbolAddress((void**)&xt_ptr, g_xt);
    cudaGetSymbolAddress((void**)&wqkvT_ptr, g_wqkvT);
    cudaGetSymbolAddress((void**)&wprojT_ptr, g_wprojT);

    cudaFuncSetAttribute(gemm_mma_kernel,
                         cudaFuncAttributeMaxDynamicSharedMemorySize, GMM_SMEM_BYTES);
    cudaFuncSetAttribute(flash_mma_kernel,
                         cudaFuncAttributeMaxDynamicSharedMemorySize, FK_SMEM_BYTES);

    // 1. RoPE tables
    rope_tables_kernel<<<(NT * 64 + 255) / 256, 256>>>();

    // 2. tf32-rounded operands
    {
        int n4 = BT * NC / 4;
        cvt_copy_kernel<<<(n4 + 255) / 256, 256>>>((const float4*)x, (float4*)xt_ptr, n4);
        dim3 blk(32, 8);
        transpose_kernel<<<dim3(C3 / 32, NC / 32), blk>>>(w_qkv, wqkvT_ptr, NC, C3);
        transpose_kernel<<<dim3(NC / 32, NC / 32), blk>>>(w_proj, wprojT_ptr, NC, NC);
    }

    // 3. qkv = x @ w_qkv (tf32 mma)
    {
        dim3 grid(C3 / 128, BT / 128);
        gemm_mma_kernel<<<grid, 256, GMM_SMEM_BYTES>>>(xt_ptr, wqkvT_ptr, qkv_ptr, BT, C3, NC);
    }

    // 4. RMSNorm + RoPE (+ tf32 rounding of q,k,v)
    rmsrope_kernel<<<BT, 256>>>(qw, kw);

    // 5. flash attention (tf32 mma)
    {
        dim3 grid(NT / 64, NB * NH);
        flash_mma_kernel<<<grid, 256, FK_SMEM_BYTES>>>();
    }

    // 6. out = y @ w_proj (tf32 mma)
    {
        dim3 grid(NC / 128, BT / 128);
        gemm_mma_kernel<<<grid, 256, GMM_SMEM_BYTES>>>(y_ptr, wprojT_ptr, out, BT, NC, NC);
    }
}

// round 6
// speedup vs baseline: 3.6001x; 1.0554x over previous
#include <cuda_runtime.h>
#include <math.h>
#include <stdint.h>

// ---------------- problem constants ----------------
#define NB 2
#define NT 2048
#define NC 2048
#define NH 16
#define ND 128
#define C3 (3 * NC)      /* 6144 */
#define BT (NB * NT)     /* 4096 */

#define RMS_EPS 1.1920929e-07f
#define SM_SCALE (1.0f / 128.0f)

// ---------------- scratch (device globals; no allocs allowed) ----------------
__device__ float g_qkv[(size_t)BT * C3];      // ~100.7 MB
__device__ float g_y[(size_t)BT * NC];        // ~33.6 MB  (tf32-rounded by flash epilogue)
__device__ float g_xt[(size_t)BT * NC];       // ~33.6 MB  (x, tf32-rounded)
__device__ float g_wqkvT[(size_t)C3 * NC];    // ~50.3 MB  (w_qkv^T, tf32-rounded)
__device__ float g_wprojT[(size_t)NC * NC];   // ~16.8 MB  (w_proj^T, tf32-rounded)
__device__ float g_cos[NT * 64];
__device__ float g_sin[NT * 64];

// ---------------- helpers ----------------
__device__ __forceinline__ float tf32r(float x) {
    uint32_t o;
    asm("cvt.rna.tf32.f32 %0, %1;" : "=r"(o) : "f"(x));
    return __uint_as_float(o);
}

__device__ __forceinline__ void mma_tf32(float c[4],
                                         uint32_t a0, uint32_t a1, uint32_t a2, uint32_t a3,
                                         uint32_t b0, uint32_t b1) {
    asm volatile(
        "mma.sync.aligned.m16n8k8.row.col.f32.tf32.tf32.f32 "
        "{%0,%1,%2,%3}, {%4,%5,%6,%7}, {%8,%9}, {%0,%1,%2,%3};"
        : "+f"(c[0]), "+f"(c[1]), "+f"(c[2]), "+f"(c[3])
        : "r"(a0), "r"(a1), "r"(a2), "r"(a3), "r"(b0), "r"(b1));
}

__device__ __forceinline__ uint32_t smem_u32(const void* p) {
    uint32_t a;
    asm("{ .reg .u64 t; cvta.to.shared.u64 t, %1; cvt.u32.u64 %0, t; }"
        : "=r"(a) : "l"(p));
    return a;
}

__device__ __forceinline__ void cp_async16(uint32_t dst, const void* src) {
    asm volatile("cp.async.cg.shared.global [%0], [%1], 16;" :: "r"(dst), "l"(src));
}
#define CP_COMMIT() asm volatile("cp.async.commit_group;" ::: "memory")
#define CP_WAIT0()  asm volatile("cp.async.wait_group 0;" ::: "memory")
#define CP_WAIT1()  asm volatile("cp.async.wait_group 1;" ::: "memory")

// ============================================================
// RoPE tables (double precision; tiny kernel)
// ============================================================
__global__ void rope_tables_kernel() {
    int idx = blockIdx.x * blockDim.x + threadIdx.x;
    if (idx >= NT * 64) return;
    int t = idx >> 6;
    int i = idx & 63;
    double inv_f = exp(-((double)i / 64.0) * log(1.0e6));
    double ang = (double)t * inv_f;
    g_cos[idx] = (float)cos(ang);
    g_sin[idx] = (float)sin(ang);
}

// ============================================================
// tf32-round copy
// ============================================================
__global__ __launch_bounds__(256) void cvt_copy_kernel(
    const float4* __restrict__ in, float4* __restrict__ out, int n4)
{
    int i = blockIdx.x * blockDim.x + threadIdx.x;
    if (i >= n4) return;
    float4 v = in[i];
    v.x = tf32r(v.x); v.y = tf32r(v.y); v.z = tf32r(v.z); v.w = tf32r(v.w);
    out[i] = v;
}

// ============================================================
// Transpose + tf32 round: out[C][R] = tf32(in[R][C])
// ============================================================
__global__ __launch_bounds__(256) void transpose_kernel(
    const float* __restrict__ in, float* __restrict__ out, int R, int Ccols)
{
    __shared__ float tile[32][33];
    int c0 = blockIdx.x * 32, r0 = blockIdx.y * 32;
    int tx = threadIdx.x, ty = threadIdx.y;
#pragma unroll
    for (int j = 0; j < 32; j += 8)
        tile[ty + j][tx] = in[(size_t)(r0 + ty + j) * Ccols + c0 + tx];
    __syncthreads();
#pragma unroll
    for (int j = 0; j < 32; j += 8)
        out[(size_t)(c0 + ty + j) * R + r0 + tx] = tf32r(tile[tx][ty + j]);
}

// ============================================================
// tf32 mma.sync GEMM v2: C[M,N] = A[M,K] @ Bt[N,K]^T
// Block tile 128x256, BK=32, 8 warps (2m x 4n), warp tile 64x64.
// 3-stage cp.async pipeline. smem: 3 * (A 128x36 + B 256x36) floats.
// ============================================================
#define G2_BM 128
#define G2_BN 256
#define G2_STG_FLOATS 13824                 /* 4608 + 9216 */
#define G2_STG_BYTES  55296
#define G2_SMEM_BYTES (3 * G2_STG_BYTES)    /* 165888 */

__global__ __launch_bounds__(256, 1) void gemm_mma2_kernel(
    const float* __restrict__ A, const float* __restrict__ Bt,
    float* __restrict__ Cm, int M, int N, int K)
{
    extern __shared__ float sm[];
    const uint32_t smb = smem_u32(sm);

    const int tid = threadIdx.x;
    const int wid = tid >> 5;
    const int lane = tid & 31;
    const int gid = lane >> 2;
    const int tig = lane & 3;
    const int warp_m = wid & 1;      // 2 m-warps, 64 rows each
    const int warp_n = wid >> 1;     // 4 n-warps, 64 cols each
    const int m0 = blockIdx.y << 7;
    const int n0 = blockIdx.x << 8;

    const int ar = tid >> 3;         // 0..31
    const int ak = (tid & 7) << 2;   // 0,4,...,28

    float acc[4][8][4];
#pragma unroll
    for (int i = 0; i < 4; i++)
#pragma unroll
        for (int j = 0; j < 8; j++)
#pragma unroll
            for (int e = 0; e < 4; e++) acc[i][j][e] = 0.0f;

    const int nt = K >> 5;           // 64

    // ---- cp.async stage issue ----
    // A rows: ar + 32i (i<4); B rows: ar + 32i (i<8). dst stride 36 floats.
#define G2_ISSUE(t_)                                                          \
    do {                                                                      \
        const int _k0 = (t_) << 5;                                            \
        const uint32_t _sb = smb + ((t_) % 3) * G2_STG_BYTES;                 \
        _Pragma("unroll")                                                     \
        for (int _i = 0; _i < 4; _i++) {                                      \
            int _r = ar + (_i << 5);                                          \
            cp_async16(_sb + (_r * 36 + ak) * 4,                              \
                       A + (size_t)(m0 + _r) * K + _k0 + ak);                 \
        }                                                                     \
        _Pragma("unroll")                                                     \
        for (int _i = 0; _i < 8; _i++) {                                      \
            int _r = ar + (_i << 5);                                          \
            cp_async16(_sb + 18432 + (_r * 36 + ak) * 4,                      \
                       Bt + (size_t)(n0 + _r) * K + _k0 + ak);                \
        }                                                                     \
    } while (0)

    G2_ISSUE(0); CP_COMMIT();
    G2_ISSUE(1); CP_COMMIT();

    const int mbase = warp_m << 6;
    const int nbase = warp_n << 6;

    for (int t = 0; t < nt; t++) {
        CP_WAIT1();
        __syncthreads();
        if (t + 2 < nt) G2_ISSUE(t + 2);
        CP_COMMIT();

        const uint32_t* Au = (const uint32_t*)(sm + (t % 3) * G2_STG_FLOATS);
        const uint32_t* Bu = Au + 4608;
#pragma unroll
        for (int ks = 0; ks < 4; ks++) {
            const int kb = ks << 3;
            uint32_t af[4][4];
#pragma unroll
            for (int mf = 0; mf < 4; mf++) {
                int r0_ = (mbase + (mf << 4) + gid) * 36 + kb + tig;
                af[mf][0] = Au[r0_];
                af[mf][1] = Au[r0_ + 8 * 36];
                af[mf][2] = Au[r0_ + 4];
                af[mf][3] = Au[r0_ + 8 * 36 + 4];
            }
            uint32_t bf[8][2];
#pragma unroll
            for (int nf = 0; nf < 8; nf++) {
                int nr = (nbase + (nf << 3) + gid) * 36 + kb + tig;
                bf[nf][0] = Bu[nr];
                bf[nf][1] = Bu[nr + 4];
            }
#pragma unroll
            for (int mf = 0; mf < 4; mf++)
#pragma unroll
                for (int nf = 0; nf < 8; nf++)
                    mma_tf32(acc[mf][nf], af[mf][0], af[mf][1], af[mf][2], af[mf][3],
                             bf[nf][0], bf[nf][1]);
        }
        __syncthreads();
    }
#undef G2_ISSUE

    // epilogue: direct float2 stores
#pragma unroll
    for (int mf = 0; mf < 4; mf++) {
#pragma unroll
        for (int nf = 0; nf < 8; nf++) {
            int r0_ = m0 + mbase + (mf << 4) + gid;
            int c = n0 + nbase + (nf << 3) + (tig << 1);
            *(float2*)&Cm[(size_t)r0_ * N + c] = make_float2(acc[mf][nf][0], acc[mf][nf][1]);
            *(float2*)&Cm[(size_t)(r0_ + 8) * N + c] = make_float2(acc[mf][nf][2], acc[mf][nf][3]);
        }
    }
}

// ============================================================
// RMSNorm + RoPE in-place on q,k; tf32-round q,k,v.
// ============================================================
__global__ __launch_bounds__(256) void rmsrope_kernel(
    const float* __restrict__ qw, const float* __restrict__ kw)
{
    const int tok = blockIdx.x;
    const int t = tok & (NT - 1);
    const int warp = threadIdx.x >> 5;
    const int lane = threadIdx.x & 31;

    const float c0 = g_cos[t * 64 + lane];
    const float s0 = g_sin[t * 64 + lane];
    const float c1 = g_cos[t * 64 + 32 + lane];
    const float s1 = g_sin[t * 64 + 32 + lane];

#pragma unroll
    for (int s = 0; s < 4; s++) {
        int task = warp + (s << 3);
        int isK = task >> 4;
        int h = task & 15;
        const float* w = isK ? kw : qw;
        size_t rbase = (size_t)tok * C3 + (size_t)isK * 2048 + (size_t)h * ND;

        float x0 = g_qkv[rbase + lane];
        float x1 = g_qkv[rbase + lane + 32];
        float x2 = g_qkv[rbase + lane + 64];
        float x3 = g_qkv[rbase + lane + 96];

        float ss = x0 * x0 + x1 * x1 + x2 * x2 + x3 * x3;
#pragma unroll
        for (int off = 16; off > 0; off >>= 1)
            ss += __shfl_xor_sync(0xffffffffu, ss, off);
        float inv = 1.0f / sqrtf(ss * (1.0f / (float)ND) + RMS_EPS);

        float n0 = x0 * inv * w[lane];
        float n1 = x1 * inv * w[lane + 32];
        float n2 = x2 * inv * w[lane + 64];
        float n3 = x3 * inv * w[lane + 96];

        g_qkv[rbase + lane]       = tf32r(n0 * c0 - n2 * s0);
        g_qkv[rbase + lane + 32]  = tf32r(n1 * c1 - n3 * s1);
        g_qkv[rbase + lane + 64]  = tf32r(n2 * c0 + n0 * s0);
        g_qkv[rbase + lane + 96]  = tf32r(n3 * c1 + n1 * s1);
    }

    // tf32-round the V section of this token
    {
        float4* vsec = (float4*)&g_qkv[(size_t)tok * C3 + 4096];
#pragma unroll
        for (int i = 0; i < 2; i++) {
            int idx = threadIdx.x + (i << 8);
            float4 v = vsec[idx];
            v.x = tf32r(v.x); v.y = tf32r(v.y); v.z = tf32r(v.z); v.w = tf32r(v.w);
            vsec[idx] = v;
        }
    }
}

// ============================================================
// Flash attention with tf32 mma.sync (causal, scale = 1/D).
// (unchanged from R4 — passed at 4.8e-4)
// ============================================================
#define FK_QS   0
#define FK_STG  17152
#define FK_KS(s) (8448 + (s) * FK_STG)
#define FK_VS(s) (8448 + (s) * FK_STG + 8448)
#define FK_PS   42752
#define FK_RM   47104
#define FK_RS   47232
#define FK_FLOATS 47360
#define FK_SMEM_BYTES (FK_FLOATS * 4)

__global__ __launch_bounds__(256, 1) void flash_mma_kernel()
{
    extern __shared__ float sm[];
    const uint32_t smb = smem_u32(sm);

    const int tid = threadIdx.x;
    const int lane = tid & 31;
    const int wid = tid >> 5;
    const int gid = lane >> 2;
    const int tig = lane & 3;
    const int wm = wid & 3;
    const int wn = wid >> 2;
    const int mbase = wm << 4;

    const int qb = blockIdx.x;
    const int bh = blockIdx.y;
    const int b = bh >> 4;
    const int h = bh & 15;
    const int q0 = qb << 6;

    const size_t base = (size_t)b * NT * C3 + (size_t)h * ND;

#pragma unroll
    for (int i = 0; i < 8; i++) {
        int f = tid + (i << 8);
        int r = f >> 5;
        int d4 = (f & 31) << 2;
        float4 v = *(const float4*)&g_qkv[base + (size_t)(q0 + r) * C3 + d4];
        *(float4*)&sm[FK_QS + r * 132 + d4] = v;
    }

    {
        const int k0 = 0, bufi = 0;
#pragma unroll
        for (int i = 0; i < 8; i++) {
            int f = tid + (i << 8);
            int r = f >> 5;
            int d4 = (f & 31) << 2;
            const float* srcK = &g_qkv[base + (size_t)(k0 + r) * C3 + 2048 + d4];
            const float* srcV = &g_qkv[base + (size_t)(k0 + r) * C3 + 4096 + d4];
            cp_async16(smb + (FK_KS(bufi) + r * 132 + d4) * 4, srcK);
            cp_async16(smb + (FK_VS(bufi) + r * 136 + d4) * 4, srcV);
        }
        CP_COMMIT();
    }

    float o[8][4];
#pragma unroll
    for (int j = 0; j < 8; j++)
#pragma unroll
        for (int e = 0; e < 4; e++) o[j][e] = 0.0f;
    float m0_ = -INFINITY, m1_ = -INFINITY, l0_ = 0.0f, l1_ = 0.0f;

    const uint32_t* Qu = (const uint32_t*)(sm + FK_QS);
    uint32_t* Pu = (uint32_t*)(sm + FK_PS);
    float* Pf = sm + FK_PS;
    float* redm = sm + FK_RM;
    float* reds = sm + FK_RS;

    for (int kt = 0; kt <= qb; kt++) {
        CP_WAIT0();
        __syncthreads();
        if (kt < qb) {
            const int k0n = (kt + 1) << 6;
            const int bufn = (kt + 1) & 1;
#pragma unroll
            for (int i = 0; i < 8; i++) {
                int f = tid + (i << 8);
                int r = f >> 5;
                int d4 = (f & 31) << 2;
                const float* srcK = &g_qkv[base + (size_t)(k0n + r) * C3 + 2048 + d4];
                const float* srcV = &g_qkv[base + (size_t)(k0n + r) * C3 + 4096 + d4];
                cp_async16(smb + (FK_KS(bufn) + r * 132 + d4) * 4, srcK);
                cp_async16(smb + (FK_VS(bufn) + r * 136 + d4) * 4, srcV);
            }
            CP_COMMIT();
        }

        const int bufi = kt & 1;
        const uint32_t* Ku = (const uint32_t*)(sm + FK_KS(bufi));
        const uint32_t* Vu = (const uint32_t*)(sm + FK_VS(bufi));
        const int k0 = kt << 6;

        float s[4][4];
#pragma unroll
        for (int j = 0; j < 4; j++)
#pragma unroll
            for (int e = 0; e < 4; e++) s[j][e] = 0.0f;

#pragma unroll
        for (int kb = 0; kb < 128; kb += 8) {
            int ai = (mbase + gid) * 132 + kb + tig;
            uint32_t a0 = Qu[ai];
            uint32_t a1 = Qu[ai + 8 * 132];
            uint32_t a2 = Qu[ai + 4];
            uint32_t a3 = Qu[ai + 8 * 132 + 4];
#pragma unroll
            for (int j = 0; j < 4; j++) {
                int nr = ((wn << 5) + (j << 3) + gid) * 132 + kb + tig;
                uint32_t b0 = Ku[nr];
                uint32_t b1 = Ku[nr + 4];
                mma_tf32(s[j], a0, a1, a2, a3, b0, b1);
            }
        }

        const int r0g = q0 + mbase + gid;
        const int r1g = r0g + 8;
        if (kt == qb) {
#pragma unroll
            for (int j = 0; j < 4; j++) {
                int cbase = k0 + (wn << 5) + (j << 3) + (tig << 1);
                s[j][0] = (cbase     <= r0g) ? s[j][0] * SM_SCALE : -1e30f;
                s[j][1] = (cbase + 1 <= r0g) ? s[j][1] * SM_SCALE : -1e30f;
                s[j][2] = (cbase     <= r1g) ? s[j][2] * SM_SCALE : -1e30f;
                s[j][3] = (cbase + 1 <= r1g) ? s[j][3] * SM_SCALE : -1e30f;
            }
        } else {
#pragma unroll
            for (int j = 0; j < 4; j++) {
                s[j][0] *= SM_SCALE; s[j][1] *= SM_SCALE;
                s[j][2] *= SM_SCALE; s[j][3] *= SM_SCALE;
            }
        }

        float pm0 = fmaxf(fmaxf(s[0][0], s[0][1]), fmaxf(s[1][0], s[1][1]));
        pm0 = fmaxf(pm0, fmaxf(fmaxf(s[2][0], s[2][1]), fmaxf(s[3][0], s[3][1])));
        float pm1 = fmaxf(fmaxf(s[0][2], s[0][3]), fmaxf(s[1][2], s[1][3]));
        pm1 = fmaxf(pm1, fmaxf(fmaxf(s[2][2], s[2][3]), fmaxf(s[3][2], s[3][3])));
        pm0 = fmaxf(pm0, __shfl_xor_sync(0xffffffffu, pm0, 1));
        pm0 = fmaxf(pm0, __shfl_xor_sync(0xffffffffu, pm0, 2));
        pm1 = fmaxf(pm1, __shfl_xor_sync(0xffffffffu, pm1, 1));
        pm1 = fmaxf(pm1, __shfl_xor_sync(0xffffffffu, pm1, 2));
        if (tig == 0) {
            redm[(wn << 6) + mbase + gid] = pm0;
            redm[(wn << 6) + mbase + gid + 8] = pm1;
        }
        __syncthreads();
        float mn0 = fmaxf(m0_, fmaxf(pm0, redm[((wn ^ 1) << 6) + mbase + gid]));
        float mn1 = fmaxf(m1_, fmaxf(pm1, redm[((wn ^ 1) << 6) + mbase + gid + 8]));
        float corr0 = __expf(m0_ - mn0);
        float corr1 = __expf(m1_ - mn1);

        float ps0 = 0.0f, ps1 = 0.0f;
#pragma unroll
        for (int j = 0; j < 4; j++) {
            float p00 = __expf(s[j][0] - mn0);
            float p01 = __expf(s[j][1] - mn0);
            float p10 = __expf(s[j][2] - mn1);
            float p11 = __expf(s[j][3] - mn1);
            ps0 += p00 + p01;
            ps1 += p10 + p11;
            int c = (wn << 5) + (j << 3) + (tig << 1);
            *(float2*)&Pf[(mbase + gid) * 68 + c] = make_float2(tf32r(p00), tf32r(p01));
            *(float2*)&Pf[(mbase + gid + 8) * 68 + c] = make_float2(tf32r(p10), tf32r(p11));
        }
        ps0 += __shfl_xor_sync(0xffffffffu, ps0, 1);
        ps0 += __shfl_xor_sync(0xffffffffu, ps0, 2);
        ps1 += __shfl_xor_sync(0xffffffffu, ps1, 1);
        ps1 += __shfl_xor_sync(0xffffffffu, ps1, 2);
        if (tig == 0) {
            reds[(wn << 6) + mbase + gid] = ps0;
            reds[(wn << 6) + mbase + gid + 8] = ps1;
        }
        __syncthreads();
        l0_ = l0_ * corr0 + ps0 + reds[((wn ^ 1) << 6) + mbase + gid];
        l1_ = l1_ * corr1 + ps1 + reds[((wn ^ 1) << 6) + mbase + gid + 8];
        m0_ = mn0; m1_ = mn1;
#pragma unroll
        for (int j = 0; j < 8; j++) {
            o[j][0] *= corr0; o[j][1] *= corr0;
            o[j][2] *= corr1; o[j][3] *= corr1;
        }

#pragma unroll
        for (int kb = 0; kb < 64; kb += 8) {
            int ai = (mbase + gid) * 68 + kb + tig;
            uint32_t a0 = Pu[ai];
            uint32_t a1 = Pu[ai + 8 * 68];
            uint32_t a2 = Pu[ai + 4];
            uint32_t a3 = Pu[ai + 8 * 68 + 4];
#pragma unroll
            for (int j = 0; j < 8; j++) {
                int dcol = (wn << 6) + (j << 3) + gid;
                uint32_t b0 = Vu[(kb + tig) * 136 + dcol];
                uint32_t b1 = Vu[(kb + tig + 4) * 136 + dcol];
                mma_tf32(o[j], a0, a1, a2, a3, b0, b1);
            }
        }
    }

    const float inv0 = 1.0f / l0_;
    const float inv1 = 1.0f / l1_;
    const int r0g = q0 + mbase + gid;
    const size_t y0 = ((size_t)b * NT + r0g) * NC + (size_t)h * ND;
    const size_t y1 = y0 + (size_t)8 * NC;
#pragma unroll
    for (int j = 0; j < 8; j++) {
        int c = (wn << 6) + (j << 3) + (tig << 1);
        *(float2*)&g_y[y0 + c] = make_float2(tf32r(o[j][0] * inv0), tf32r(o[j][1] * inv0));
        *(float2*)&g_y[y1 + c] = make_float2(tf32r(o[j][2] * inv1), tf32r(o[j][3] * inv1));
    }
}

// ============================================================
// launch
// ============================================================
extern "C" void kernel_launch(void* const* d_in, const int* in_sizes, int n_in,
                              void* d_out, int out_size)
{
    const float* x      = (const float*)d_in[0];
    const float* w_qkv  = (const float*)d_in[1];
    const float* w_proj = (const float*)d_in[2];
    const float* qw     = (const float*)d_in[3];
    const float* kw     = (const float*)d_in[4];
    float* out = (float*)d_out;

    float* qkv_ptr = nullptr;
    float* y_ptr = nullptr;
    float* xt_ptr = nullptr;
    float* wqkvT_ptr = nullptr;
    float* wprojT_ptr = nullptr;
    cudaGetSymbolAddress((void**)&qkv_ptr, g_qkv);
    cudaGetSymbolAddress((void**)&y_ptr, g_y);
    cudaGetSymbolAddress((void**)&xt_ptr, g_xt);
    cudaGetSymbolAddress((void**)&wqkvT_ptr, g_wqkvT);
    cudaGetSymbolAddress((void**)&wprojT_ptr, g_wprojT);

    cudaFuncSetAttribute(gemm_mma2_kernel,
                         cudaFuncAttributeMaxDynamicSharedMemorySize, G2_SMEM_BYTES);
    cudaFuncSetAttribute(flash_mma_kernel,
                         cudaFuncAttributeMaxDynamicSharedMemorySize, FK_SMEM_BYTES);

    // 1. RoPE tables
    rope_tables_kernel<<<(NT * 64 + 255) / 256, 256>>>();

    // 2. tf32-rounded operands
    {
        int n4 = BT * NC / 4;
        cvt_copy_kernel<<<(n4 + 255) / 256, 256>>>((const float4*)x, (float4*)xt_ptr, n4);
        dim3 blk(32, 8);
        transpose_kernel<<<dim3(C3 / 32, NC / 32), blk>>>(w_qkv, wqkvT_ptr, NC, C3);
        transpose_kernel<<<dim3(NC / 32, NC / 32), blk>>>(w_proj, wprojT_ptr, NC, NC);
    }

    // 3. qkv = x @ w_qkv (tf32 mma, 128x256 tiles)
    {
        dim3 grid(C3 / G2_BN, BT / G2_BM);
        gemm_mma2_kernel<<<grid, 256, G2_SMEM_BYTES>>>(xt_ptr, wqkvT_ptr, qkv_ptr, BT, C3, NC);
    }

    // 4. RMSNorm + RoPE (+ tf32 rounding of q,k,v)
    rmsrope_kernel<<<BT, 256>>>(qw, kw);

    // 5. flash attention (tf32 mma)
    {
        dim3 grid(NT / 64, NB * NH);
        flash_mma_kernel<<<grid, 256, FK_SMEM_BYTES>>>();
    }

    // 6. out = y @ w_proj (tf32 mma, 128x256 tiles)
    {
        dim3 grid(NC / G2_BN, BT / G2_BM);
        gemm_mma2_kernel<<<grid, 256, G2_SMEM_BYTES>>>(y_ptr, wprojT_ptr, out, BT, NC, NC);
    }
}